// round 5
// baseline (speedup 1.0000x reference)
#include <cuda_runtime.h>
#include <math.h>
#include <stdint.h>

#define TT   1024
#define BB   512
#define DIN  128
#define HH   512
#define DOUT 128

#define NG   16      // batch groups
#define NS   8       // j slices
#define MB   32      // batch rows per group
#define JS   64      // hidden outputs per slice
#define KT   640     // unified reduction: [0,512)=h, [512,640)=x
#define CHUNK 128
#define NCH  5
#define NTHR 512

#define WP   644     // w_s row pitch (floats): 2576B = 16 mod 128 -> conflict-free
#define VP   132     // v_s chunk row pitch:     528B = 16 mod 128
#define VP2  260     // epilogue row pitch:     1040B = 16 mod 128

// Cross-CTA hidden-state exchange buffers (double-buffered by step parity)
__device__ float    g_hbuf[2][BB][HH];   // 2 MB, L2-resident
__device__ unsigned g_cnt[NG * 32];      // per-group barrier counters, 128B apart

__global__ void zero_kernel() {
    int i = blockIdx.x * blockDim.x + threadIdx.x;
    int stride = gridDim.x * blockDim.x;
    float* p = &g_hbuf[0][0][0];
    for (int k = i; k < BB * HH; k += stride) p[k] = 0.f;
    if (i < NG * 32) g_cnt[i] = 0u;
}

__device__ __forceinline__ void lds_v2(uint64_t& a, uint64_t& b, uint32_t addr) {
    asm volatile("ld.shared.v2.u64 {%0,%1}, [%2];" : "=l"(a), "=l"(b) : "r"(addr));
}
#define FMA2(acc, w, h) \
    asm("fma.rn.f32x2 %0, %1, %2, %0;" : "+l"(acc) : "l"(w), "l"(h))

__device__ __forceinline__ float2 unpack2(uint64_t a) {
    float lo, hi;
    asm("mov.b64 {%0,%1}, %2;" : "=f"(lo), "=f"(hi) : "l"(a));
    return make_float2(lo, hi);
}

__global__ __launch_bounds__(NTHR, 1) void scan_kernel(
    const float* __restrict__ x,
    const float* __restrict__ Wx,
    const float* __restrict__ bx,
    const float* __restrict__ Wh,
    const float* __restrict__ bh,
    const float* __restrict__ Wy,
    const float* __restrict__ by,
    float* __restrict__ y)
{
    extern __shared__ float sm[];
    float* w_s = sm;                 // [JS][WP]
    float* v_s = sm + JS * WP;       // 2 chunk buffers [2][MB][VP] / epi [MB][VP2]

    const int tid = threadIdx.x;
    const int g   = blockIdx.x >> 3;   // batch group
    const int s   = blockIdx.x & 7;    // j slice

    // compute-tile decode: thread owns j in {jp, jp+32}, m in {mh, mh+16}
    const int jp = (tid & 7) | (((tid >> 5) & 3) << 3);   // 0..31
    const int mh = ((tid >> 3) & 3) | (((tid >> 7) & 3) << 2); // 0..15

    // loader decode
    const int rr = tid >> 4;          // 0..31 (row)
    const int cb = tid & 15;          // 0..15 (col4 base)

    // ---- load unified weight slice into smem (once) ----
    const float4* Wh4 = reinterpret_cast<const float4*>(Wh);
    const float4* Wx4 = reinterpret_cast<const float4*>(Wx);
    for (int i = tid; i < JS * (HH / 4); i += NTHR) {
        int jl = i >> 7, c4 = i & 127;
        float4 w = Wh4[(size_t)(s * JS + jl) * (HH / 4) + c4];
        *reinterpret_cast<float4*>(&w_s[jl * WP + c4 * 4]) = w;
    }
    for (int i = tid; i < JS * (DIN / 4); i += NTHR) {
        int jl = i >> 5, c4 = i & 31;
        float4 w = Wx4[(size_t)(s * JS + jl) * (DIN / 4) + c4];
        *reinterpret_cast<float4*>(&w_s[jl * WP + HH + c4 * 4]) = w;
    }
    const int jg0 = s * JS + jp, jg1 = jg0 + 32;
    const float bias0 = bx[jg0] + bh[jg0];
    const float bias1 = bx[jg1] + bh[jg1];
    __syncthreads();

    const uint32_t w_sh = (uint32_t)__cvta_generic_to_shared(w_s);
    const uint32_t v_sh = (uint32_t)__cvta_generic_to_shared(v_s);
    unsigned* cnt = &g_cnt[g * 32];

    const float* __restrict__ hrow_x =
        &x[(size_t)(g * MB + rr) * TT * DIN];

    float4 pre[2];
    int p = 0;

    for (int t = 0; t < TT; ++t) {
        uint64_t a00 = 0ull, a01 = 0ull, a10 = 0ull, a11 = 0ull;

        // prologue: LDG chunk 0 (pure h)
        {
            const float* hr = &g_hbuf[p][g * MB + rr][0];
            pre[0] = __ldcg(reinterpret_cast<const float4*>(hr + cb * 4));
            pre[1] = __ldcg(reinterpret_cast<const float4*>(hr + (cb + 16) * 4));
        }

        #pragma unroll
        for (int c = 0; c < NCH; ++c) {
            const int vb = c & 1;
            // stage chunk c
            {
                float* vrow = &v_s[(vb * MB + rr) * VP];
                *reinterpret_cast<float4*>(vrow + cb * 4)        = pre[0];
                *reinterpret_cast<float4*>(vrow + (cb + 16) * 4) = pre[1];
            }
            __syncthreads();
            // prefetch chunk c+1
            if (c + 1 < NCH) {
                if (c + 1 < 4) {
                    const float* hr = &g_hbuf[p][g * MB + rr][(c + 1) * CHUNK];
                    pre[0] = __ldcg(reinterpret_cast<const float4*>(hr + cb * 4));
                    pre[1] = __ldcg(reinterpret_cast<const float4*>(hr + (cb + 16) * 4));
                } else {
                    const float* xr = hrow_x + (size_t)t * DIN;
                    pre[0] = __ldg(reinterpret_cast<const float4*>(xr + cb * 4));
                    pre[1] = __ldg(reinterpret_cast<const float4*>(xr + (cb + 16) * 4));
                }
            }
            // compute chunk c: 32 k-quads
            const uint32_t wa0 = w_sh + (uint32_t)((jp * WP + c * CHUNK) * 4);
            const uint32_t wa1 = wa0 + (uint32_t)(32 * WP * 4);
            const uint32_t ha0 = v_sh + (uint32_t)((vb * MB + mh) * VP * 4);
            const uint32_t ha1 = ha0 + (uint32_t)(16 * VP * 4);

            #pragma unroll 8
            for (int q = 0; q < CHUNK / 4; ++q) {
                uint64_t w0l, w0h, w1l, w1h, h0l, h0h, h1l, h1h;
                lds_v2(w0l, w0h, wa0 + q * 16);
                lds_v2(w1l, w1h, wa1 + q * 16);
                lds_v2(h0l, h0h, ha0 + q * 16);
                lds_v2(h1l, h1h, ha1 + q * 16);
                FMA2(a00, w0l, h0l); FMA2(a00, w0h, h0h);
                FMA2(a01, w0l, h1l); FMA2(a01, w0h, h1h);
                FMA2(a10, w1l, h0l); FMA2(a10, w1h, h0h);
                FMA2(a11, w1l, h1l); FMA2(a11, w1h, h1h);
            }
        }

        // finalize: reduce halves, bias, tanh, publish
        const int q2 = p ^ 1;
        {
            float2 v;
            v = unpack2(a00);
            g_hbuf[q2][g * MB + mh     ][jg0] = tanhf(v.x + v.y + bias0);
            v = unpack2(a01);
            g_hbuf[q2][g * MB + mh + 16][jg0] = tanhf(v.x + v.y + bias0);
            v = unpack2(a10);
            g_hbuf[q2][g * MB + mh     ][jg1] = tanhf(v.x + v.y + bias1);
            v = unpack2(a11);
            g_hbuf[q2][g * MB + mh + 16][jg1] = tanhf(v.x + v.y + bias1);
        }
        __threadfence();
        if (tid == 0) {
            atomicAdd(cnt, 1u);
            const unsigned tgt = (unsigned)(NS * (t + 1));
            unsigned v;
            do {
                asm volatile("ld.acquire.gpu.global.u32 %0, [%1];"
                             : "=r"(v) : "l"(cnt));
                if (v < tgt) __nanosleep(64);
            } while (v < tgt);
        }
        __syncthreads();
        p ^= 1;
    }

    // ---- epilogue: y[b, o] = by[o] + sum_k Wy[o,k]*h_T[b,k]; h_T in g_hbuf[0]
    const int oc = tid & 15;          // 0..15
    const int me = tid >> 4;          // 0..31 (this thread's batch row)
    const int o  = s * 16 + oc;
    const ulonglong2* Wy2 = reinterpret_cast<const ulonglong2*>(Wy);
    uint64_t ya = 0ull;

    #pragma unroll
    for (int c = 0; c < 2; ++c) {
        __syncthreads();
        #pragma unroll
        for (int q = 0; q < 4; ++q) {
            int c4 = oc + 16 * q;     // 0..63 float4 within 256-float chunk
            float4 vv = __ldcg(reinterpret_cast<const float4*>(
                            &g_hbuf[0][g * MB + me][c * 256 + c4 * 4]));
            *reinterpret_cast<float4*>(&v_s[me * VP2 + c4 * 4]) = vv;
        }
        __syncthreads();
        const uint32_t hb = v_sh + (uint32_t)(me * VP2 * 4);
        #pragma unroll 8
        for (int k4 = 0; k4 < 64; ++k4) {
            uint64_t hl, hh;
            lds_v2(hl, hh, hb + k4 * 16);
            ulonglong2 w = __ldg(&Wy2[(size_t)o * 128 + c * 64 + k4]);
            FMA2(ya, w.x, hl);
            FMA2(ya, w.y, hh);
        }
    }
    {
        float2 a = unpack2(ya);
        y[(size_t)(g * MB + me) * DOUT + o] = by[o] + a.x + a.y;
    }
}

extern "C" void kernel_launch(void* const* d_in, const int* in_sizes, int n_in,
                              void* d_out, int out_size) {
    const float* x  = (const float*)d_in[0];
    const float* Wx = (const float*)d_in[1];
    const float* bx = (const float*)d_in[2];
    const float* Wh = (const float*)d_in[3];
    const float* bh = (const float*)d_in[4];
    const float* Wy = (const float*)d_in[5];
    const float* by = (const float*)d_in[6];
    float* y = (float*)d_out;

    // smem: weights 64*644 + max(chunk bufs 2*32*132, epi 32*260) floats
    int vfloats = 2 * MB * VP;
    if (MB * VP2 > vfloats) vfloats = MB * VP2;
    const int smem_bytes = (JS * WP + vfloats) * (int)sizeof(float);
    cudaFuncSetAttribute(scan_kernel,
                         cudaFuncAttributeMaxDynamicSharedMemorySize, smem_bytes);

    zero_kernel<<<256, 256>>>();
    scan_kernel<<<NG * NS, NTHR, smem_bytes>>>(x, Wx, bx, Wh, bh, Wy, by, y);
}

// round 6
// speedup vs baseline: 1.2021x; 1.2021x over previous
#include <cuda_runtime.h>
#include <math.h>
#include <stdint.h>

#define TT   1024
#define BB   512
#define DIN  128
#define HH   512
#define DOUT 128

#define NG   16      // batch groups
#define NS   8       // j slices
#define MB   32      // batch rows per group
#define JS   64      // hidden outputs per slice
#define CHUNK 128
#define NTHR 256

#define WP   644     // w_s row pitch (floats): 2576B = 16 mod 128 -> conflict-free
#define VP   132     // v_s chunk row pitch:     528B = 16 mod 128
#define VP2  260     // epilogue row pitch:     1040B = 16 mod 128

// Cross-CTA hidden-state exchange (double-buffered by step parity)
__device__ float    g_hbuf[2][BB][HH];      // 2 MB, L2-resident
__device__ unsigned g_flag[NG][NS][32];     // per-slice step counters, 128B apart

__global__ void zero_kernel() {
    int i = blockIdx.x * blockDim.x + threadIdx.x;
    int stride = gridDim.x * blockDim.x;
    float* p = &g_hbuf[0][0][0];
    for (int k = i; k < BB * HH; k += stride) p[k] = 0.f;
    unsigned* f = &g_flag[0][0][0];
    for (int k = i; k < NG * NS * 32; k += stride) f[k] = 0u;
}

__device__ __forceinline__ void lds_v2(uint64_t& a, uint64_t& b, uint32_t addr) {
    asm volatile("ld.shared.v2.u64 {%0,%1}, [%2];" : "=l"(a), "=l"(b) : "r"(addr));
}
#define FMA2(acc, w, h) \
    asm("fma.rn.f32x2 %0, %1, %2, %0;" : "+l"(acc) : "l"(w), "l"(h))

__device__ __forceinline__ float2 unpack2(uint64_t a) {
    float lo, hi;
    asm("mov.b64 {%0,%1}, %2;" : "=f"(lo), "=f"(hi) : "l"(a));
    return make_float2(lo, hi);
}

__global__ __launch_bounds__(NTHR, 1) void scan_kernel(
    const float* __restrict__ x,
    const float* __restrict__ Wx,
    const float* __restrict__ bx,
    const float* __restrict__ Wh,
    const float* __restrict__ bh,
    const float* __restrict__ Wy,
    const float* __restrict__ by,
    float* __restrict__ y)
{
    extern __shared__ float sm[];
    float* w_s = sm;                 // [JS][WP]
    float* v_s = sm + JS * WP;       // chunk bufs [2][MB][VP] / epi [MB][VP2]

    const int tid = threadIdx.x;
    const int g   = blockIdx.x >> 3;   // batch group
    const int s   = blockIdx.x & 7;    // j slice

    const int jp  = tid >> 3;          // 0..31 : j in {jp, jp+32}
    const int mq  = tid & 7;           // 0..7  : m in {mq, mq+8, mq+16, mq+24}
    const int rr  = tid >> 3;          // loader row 0..31
    const int cb  = tid & 7;           // loader col4 base 0..7

    // ---- load unified weight slice into smem (once); x-weights at col 512 ----
    const float4* Wh4 = reinterpret_cast<const float4*>(Wh);
    const float4* Wx4 = reinterpret_cast<const float4*>(Wx);
    for (int i = tid; i < JS * (HH / 4); i += NTHR) {
        int jl = i >> 7, c4 = i & 127;
        float4 w = Wh4[(size_t)(s * JS + jl) * (HH / 4) + c4];
        *reinterpret_cast<float4*>(&w_s[jl * WP + c4 * 4]) = w;
    }
    for (int i = tid; i < JS * (DIN / 4); i += NTHR) {
        int jl = i >> 5, c4 = i & 31;
        float4 w = Wx4[(size_t)(s * JS + jl) * (DIN / 4) + c4];
        *reinterpret_cast<float4*>(&w_s[jl * WP + HH + c4 * 4]) = w;
    }
    const int jg0 = s * JS + jp, jg1 = jg0 + 32;
    const float bias0 = bx[jg0] + bh[jg0];
    const float bias1 = bx[jg1] + bh[jg1];
    __syncthreads();

    const uint32_t w_sh = (uint32_t)__cvta_generic_to_shared(w_s);
    const uint32_t v_sh = (uint32_t)__cvta_generic_to_shared(v_s);

    const float* __restrict__ xrow = &x[(size_t)(g * MB + rr) * TT * DIN];
    const float* __restrict__ hrow0 = &g_hbuf[0][g * MB + rr][0];
    const float* __restrict__ hrow1 = &g_hbuf[1][g * MB + rr][0];

    float4 pre[4];
    // prefetch x chunk for t=0
    #pragma unroll
    for (int qq = 0; qq < 4; ++qq)
        pre[qq] = __ldg(reinterpret_cast<const float4*>(xrow + (cb + 8 * qq) * 4));

    int p = 0;

    for (int t = 0; t < TT; ++t) {
        uint64_t accs[2][2][4];
        #pragma unroll
        for (int bk = 0; bk < 2; ++bk)
            #pragma unroll
            for (int jj = 0; jj < 2; ++jj)
                #pragma unroll
                for (int i = 0; i < 4; ++i) accs[bk][jj][i] = 0ull;

        const float* __restrict__ hr = p ? hrow1 : hrow0;

        // ---- stage x chunk (prefetched last step) into buf0 ----
        {
            float* vrow = &v_s[(0 * MB + rr) * VP];
            #pragma unroll
            for (int qq = 0; qq < 4; ++qq)
                *reinterpret_cast<float4*>(vrow + (cb + 8 * qq) * 4) = pre[qq];
        }
        __syncthreads();
        // LDG h chunk 0 (in flight under x compute)
        #pragma unroll
        for (int qq = 0; qq < 4; ++qq)
            pre[qq] = __ldcg(reinterpret_cast<const float4*>(hr + (cb + 8 * qq) * 4));

        // ---- compute macro: one 128-wide K chunk ----
        #define COMPUTE_CHUNK(KOFF, VB)                                          \
        do {                                                                     \
            const uint32_t wa0 = w_sh + (uint32_t)((jp * WP + (KOFF)) * 4);      \
            const uint32_t wa1 = wa0 + (uint32_t)(32 * WP * 4);                  \
            const uint32_t hb  = v_sh + (uint32_t)(((VB) * MB + mq) * VP * 4);   \
            _Pragma("unroll")                                                    \
            for (int q = 0; q < 32; ++q) {                                       \
                const int bk = q & 1;                                            \
                uint64_t w0l, w0h, w1l, w1h;                                     \
                lds_v2(w0l, w0h, wa0 + q * 16);                                  \
                lds_v2(w1l, w1h, wa1 + q * 16);                                  \
                _Pragma("unroll")                                                \
                for (int i = 0; i < 4; ++i) {                                    \
                    uint64_t hl, hh;                                             \
                    lds_v2(hl, hh, hb + (uint32_t)(i * 8 * VP * 4) + q * 16);    \
                    FMA2(accs[bk][0][i], w0l, hl);                               \
                    FMA2(accs[bk][0][i], w0h, hh);                               \
                    FMA2(accs[bk][1][i], w1l, hl);                               \
                    FMA2(accs[bk][1][i], w1h, hh);                               \
                }                                                                \
            }                                                                    \
        } while (0)

        // x chunk uses weight cols [512,640), staged in buf 0
        COMPUTE_CHUNK(HH, 0);

        #pragma unroll
        for (int c = 0; c < 4; ++c) {
            const int vb = (c + 1) & 1;   // h0->1, h1->0, h2->1, h3->0
            {
                float* vrow = &v_s[(vb * MB + rr) * VP];
                #pragma unroll
                for (int qq = 0; qq < 4; ++qq)
                    *reinterpret_cast<float4*>(vrow + (cb + 8 * qq) * 4) = pre[qq];
            }
            __syncthreads();
            if (c < 3) {
                #pragma unroll
                for (int qq = 0; qq < 4; ++qq)
                    pre[qq] = __ldcg(reinterpret_cast<const float4*>(
                                  hr + (c + 1) * CHUNK + (cb + 8 * qq) * 4));
            } else {
                const int tn = (t + 1 < TT) ? t + 1 : 0;   // prefetch x for next step
                const float* xr2 = xrow + (size_t)tn * DIN;
                #pragma unroll
                for (int qq = 0; qq < 4; ++qq)
                    pre[qq] = __ldg(reinterpret_cast<const float4*>(
                                  xr2 + (cb + 8 * qq) * 4));
            }
            COMPUTE_CHUNK(c * CHUNK, vb);
        }
        #undef COMPUTE_CHUNK

        // ---- finalize: merge banks, bias, tanh, publish ----
        const int q2 = p ^ 1;
        #pragma unroll
        for (int jj = 0; jj < 2; ++jj) {
            const float bb = jj ? bias1 : bias0;
            const int   jc = jj ? jg1 : jg0;
            #pragma unroll
            for (int i = 0; i < 4; ++i) {
                float2 vA = unpack2(accs[0][jj][i]);
                float2 vB = unpack2(accs[1][jj][i]);
                float hval = tanhf(vA.x + vA.y + vB.x + vB.y + bb);
                g_hbuf[q2][g * MB + mq + 8 * i][jc] = hval;
            }
        }

        // ---- cheap cross-CTA step barrier ----
        __syncthreads();                      // all h-stores issued (CTA-ordered)
        if (tid == 0) {
            // cumulative release: publishes every thread's h-stores
            asm volatile("st.release.gpu.global.u32 [%0], %1;"
                         :: "l"(&g_flag[g][s][0]), "r"((unsigned)(t + 1))
                         : "memory");
        }
        if (tid < NS) {
            const unsigned tgt = (unsigned)(t + 1);
            unsigned v;
            do {
                asm volatile("ld.acquire.gpu.global.u32 %0, [%1];"
                             : "=r"(v) : "l"(&g_flag[g][tid][0]));
            } while (v < tgt);
        }
        __syncthreads();
        p ^= 1;
    }

    // ---- epilogue: y[b, o] = by[o] + sum_k Wy[o,k]*h_T[b,k]; h_T in g_hbuf[0]
    const int oc = tid & 15;          // 0..15
    const int me = tid >> 4;          // 0..15? no: 256/16 = 16 rows... need 32
    // NOTE: 256 threads: oc 0..15 (o), me 0..15 — but MB=32 rows.
    // Use two row-passes: each thread handles rows me and me+16.
    const int o  = s * 16 + oc;
    const ulonglong2* Wy2 = reinterpret_cast<const ulonglong2*>(Wy);

    #pragma unroll
    for (int half = 0; half < 2; ++half) {
        const int mrow = me + 16 * half;
        uint64_t ya = 0ull;
        #pragma unroll
        for (int c = 0; c < 2; ++c) {
            __syncthreads();
            // stage 256-float chunk of h rows [0..15]+16*half into v_s
            #pragma unroll
            for (int qq = 0; qq < 4; ++qq) {
                int c4 = oc + 16 * qq;    // 0..63 float4
                float4 vv = __ldcg(reinterpret_cast<const float4*>(
                                &g_hbuf[0][g * MB + mrow][c * 256 + c4 * 4]));
                *reinterpret_cast<float4*>(&v_s[me * VP2 + c4 * 4]) = vv;
            }
            __syncthreads();
            const uint32_t hb = v_sh + (uint32_t)(me * VP2 * 4);
            #pragma unroll 8
            for (int k4 = 0; k4 < 64; ++k4) {
                uint64_t hl, hh;
                lds_v2(hl, hh, hb + k4 * 16);
                ulonglong2 w = __ldg(&Wy2[(size_t)o * 128 + c * 64 + k4]);
                FMA2(ya, w.x, hl);
                FMA2(ya, w.y, hh);
            }
        }
        float2 a = unpack2(ya);
        y[(size_t)(g * MB + mrow) * DOUT + o] = by[o] + a.x + a.y;
    }
}

extern "C" void kernel_launch(void* const* d_in, const int* in_sizes, int n_in,
                              void* d_out, int out_size) {
    const float* x  = (const float*)d_in[0];
    const float* Wx = (const float*)d_in[1];
    const float* bx = (const float*)d_in[2];
    const float* Wh = (const float*)d_in[3];
    const float* bh = (const float*)d_in[4];
    const float* Wy = (const float*)d_in[5];
    const float* by = (const float*)d_in[6];
    float* y = (float*)d_out;

    int vfloats = 2 * MB * VP;                 // 8448
    if (MB * VP2 > vfloats) vfloats = MB * VP2;
    const int smem_bytes = (JS * WP + vfloats) * (int)sizeof(float);
    cudaFuncSetAttribute(scan_kernel,
                         cudaFuncAttributeMaxDynamicSharedMemorySize, smem_bytes);

    zero_kernel<<<256, 256>>>();
    scan_kernel<<<NG * NS, NTHR, smem_bytes>>>(x, Wx, bx, Wh, bh, Wy, by, y);
}